// round 7
// baseline (speedup 1.0000x reference)
#include <cuda_runtime.h>
#include <cuda_bf16.h>

#define N_NODES  50000
#define N_EDGES  1600000
#define N_GRAPHS 512
#define EMB      32
#define HID      64
#define SCAN_NB  ((N_NODES + 255) / 256)   // 196

// ---------------- scratch (device globals: allocation-free) ----------------
__device__ float           g_x   [N_NODES * EMB];   // embedded features (fp32, self term)
__device__ __nv_bfloat16   g_xh  [N_NODES * EMB];   // embedded features (bf16, gather)
__device__ float           g_h1  [N_NODES * HID];   // layer-1 out (fp32, self term)
__device__ __nv_bfloat16   g_h1h [N_NODES * HID];   // layer-1 out (bf16, gather)
__device__ int   g_cnt [N_NODES];         // in-degree
__device__ int   g_ptr [N_NODES];         // CSR row starts
__device__ int   g_cur [N_NODES];         // fill cursors
__device__ int   g_nbr [N_EDGES];         // CSR adjacency (src node per slot)
__device__ int   g_bsum[256];             // scan block totals
__device__ float g_psum[N_GRAPHS * HID];  // pooled sums
__device__ float g_pcnt[N_GRAPHS];        // pooled counts

__device__ __forceinline__ void red_add_f(float* p, float v) {
    asm volatile("red.global.add.f32 [%0], %1;" :: "l"(p), "f"(v) : "memory");
}

// ---------------- init: zero counters + embedding gather (fp32 + bf16) ----------------
__global__ void k_init(const int* __restrict__ x_ids,
                       const float* __restrict__ embed) {
    int stride = gridDim.x * blockDim.x;
    int tid = blockIdx.x * blockDim.x + threadIdx.x;

    float4* xv = reinterpret_cast<float4*>(g_x);
    __nv_bfloat162* xh2 = reinterpret_cast<__nv_bfloat162*>(g_xh);
    const float4* emb4 = reinterpret_cast<const float4*>(embed);
    const int n1 = N_NODES * EMB / 4;              // 8 float4 per node
    for (int i = tid; i < n1; i += stride) {
        int node = i >> 3;
        int c    = i & 7;
        float4 v = emb4[(x_ids[node] << 3) + c];
        xv[i] = v;
        xh2[i * 2]     = __float22bfloat162_rn(make_float2(v.x, v.y));
        xh2[i * 2 + 1] = __float22bfloat162_rn(make_float2(v.z, v.w));
    }
    for (int i = tid; i < N_NODES; i += stride) g_cnt[i] = 0;
    for (int i = tid; i < N_GRAPHS * HID; i += stride) g_psum[i] = 0.f;
    for (int i = tid; i < N_GRAPHS; i += stride) g_pcnt[i] = 0.f;
}

// ---------------- CSR build: histogram, scan, fill ----------------
__global__ void k_hist(const int* __restrict__ dst) {
    int e = blockIdx.x * blockDim.x + threadIdx.x;
    if (e < N_EDGES) atomicAdd(&g_cnt[dst[e]], 1);
}

__global__ void k_scan1() {
    __shared__ int sh[256];
    int t = threadIdx.x;
    int i = blockIdx.x * 256 + t;
    int v = (i < N_NODES) ? g_cnt[i] : 0;
    sh[t] = v;
    __syncthreads();
#pragma unroll
    for (int off = 1; off < 256; off <<= 1) {
        int x = (t >= off) ? sh[t - off] : 0;
        __syncthreads();
        sh[t] += x;
        __syncthreads();
    }
    if (i < N_NODES) g_ptr[i] = sh[t] - v;   // exclusive within block
    if (t == 255) g_bsum[blockIdx.x] = sh[255];
}

// scan3 now also computes the block-offset prefix (replaces k_scan2)
__global__ void k_scan3() {
    __shared__ int s_off;
    int t = threadIdx.x;
    if (t < 32) {
        int acc = 0;
        for (int j = t; j < blockIdx.x; j += 32) acc += g_bsum[j];
#pragma unroll
        for (int o = 16; o; o >>= 1) acc += __shfl_down_sync(0xffffffffu, acc, o);
        if (t == 0) s_off = acc;
    }
    __syncthreads();
    int i = blockIdx.x * 256 + t;
    if (i < N_NODES) {
        int p = g_ptr[i] + s_off;
        g_ptr[i] = p;
        g_cur[i] = p;
    }
}

__global__ void k_fill(const int* __restrict__ src, const int* __restrict__ dst) {
    int e = blockIdx.x * blockDim.x + threadIdx.x;
    if (e < N_EDGES) {
        int p = atomicAdd(&g_cur[dst[e]], 1);
        g_nbr[p] = src[e];
    }
}

// ---------------- layer 1: bf16 gather-mean + SAGE linear + ReLU (fused) ----------------
// warp per node (grid-stride); lane = channel; matvec via warp shuffles
__global__ void __launch_bounds__(256)
k_layer1(const float* __restrict__ w_l,
         const float* __restrict__ b,
         const float* __restrict__ w_r) {
    __shared__ float s_wl[EMB * HID];
    __shared__ float s_wr[EMB * HID];
    __shared__ float s_b[HID];
    int t = threadIdx.x;
    for (int i = t; i < EMB * HID; i += blockDim.x) { s_wl[i] = w_l[i]; s_wr[i] = w_r[i]; }
    if (t < HID) s_b[t] = b[t];
    __syncthreads();

    int lane   = t & 31;
    int warp_g = (blockIdx.x * blockDim.x + t) >> 5;
    int nwarps = (gridDim.x * blockDim.x) >> 5;

    for (int node = warp_g; node < N_NODES; node += nwarps) {
        int beg = g_ptr[node];
        int n   = g_cnt[node];
        float s0 = 0.f, s1 = 0.f, s2 = 0.f, s3 = 0.f;
        int k = 0;
        for (; k + 3 < n; k += 4) {
            int n0 = __ldg(&g_nbr[beg + k]);
            int n1 = __ldg(&g_nbr[beg + k + 1]);
            int n2 = __ldg(&g_nbr[beg + k + 2]);
            int n3 = __ldg(&g_nbr[beg + k + 3]);
            s0 += __bfloat162float(g_xh[n0 * EMB + lane]);
            s1 += __bfloat162float(g_xh[n1 * EMB + lane]);
            s2 += __bfloat162float(g_xh[n2 * EMB + lane]);
            s3 += __bfloat162float(g_xh[n3 * EMB + lane]);
        }
        for (; k < n; k++)
            s0 += __bfloat162float(g_xh[__ldg(&g_nbr[beg + k]) * EMB + lane]);
        float m  = (s0 + s1) + (s2 + s3);
        m *= (n > 0) ? (1.f / (float)n) : 0.f;       // mean (deg=0 -> 0)
        float xv = g_x[node * EMB + lane];

        float a0 = s_b[lane], a1 = s_b[lane + 32];
#pragma unroll
        for (int kk = 0; kk < EMB; kk++) {
            float mk = __shfl_sync(0xffffffffu, m,  kk);
            float xk = __shfl_sync(0xffffffffu, xv, kk);
            a0 = fmaf(mk, s_wl[kk * HID + lane],      fmaf(xk, s_wr[kk * HID + lane],      a0));
            a1 = fmaf(mk, s_wl[kk * HID + lane + 32], fmaf(xk, s_wr[kk * HID + lane + 32], a1));
        }
        a0 = fmaxf(a0, 0.f);
        a1 = fmaxf(a1, 0.f);
        g_h1[node * HID + lane]       = a0;
        g_h1[node * HID + lane + 32]  = a1;
        g_h1h[node * HID + lane]      = __float2bfloat16_rn(a0);
        g_h1h[node * HID + lane + 32] = __float2bfloat16_rn(a1);
    }
}

// ---------------- layer 2: bf16 gather-mean + SAGE linear + ReLU + pool (fused) ----------------
// lane holds channel pair (2*lane, 2*lane+1) for the gather; outputs (lane, lane+32)
__global__ void __launch_bounds__(256)
k_layer2(const int* __restrict__ batch,
         const float* __restrict__ w_l,
         const float* __restrict__ b,
         const float* __restrict__ w_r) {
    __shared__ float s_wl[HID * HID];
    __shared__ float s_wr[HID * HID];
    __shared__ float s_b[HID];
    int t = threadIdx.x;
    for (int i = t; i < HID * HID; i += blockDim.x) { s_wl[i] = w_l[i]; s_wr[i] = w_r[i]; }
    if (t < HID) s_b[t] = b[t];
    __syncthreads();

    int lane   = t & 31;
    int warp_g = (blockIdx.x * blockDim.x + t) >> 5;
    int nwarps = (gridDim.x * blockDim.x) >> 5;

    const __nv_bfloat162* H2 = reinterpret_cast<const __nv_bfloat162*>(g_h1h);
    const float2*         G2 = reinterpret_cast<const float2*>(g_h1);

    for (int node = warp_g; node < N_NODES; node += nwarps) {
        int beg = g_ptr[node];
        int n   = g_cnt[node];
        float eA = 0.f, oA = 0.f, eB = 0.f, oB = 0.f;
        int k = 0;
        for (; k + 1 < n; k += 2) {
            int n0 = __ldg(&g_nbr[beg + k]);
            int n1 = __ldg(&g_nbr[beg + k + 1]);
            float2 f0 = __bfloat1622float2(H2[n0 * 32 + lane]);
            float2 f1 = __bfloat1622float2(H2[n1 * 32 + lane]);
            eA += f0.x; oA += f0.y;
            eB += f1.x; oB += f1.y;
        }
        for (; k < n; k++) {
            int nb = __ldg(&g_nbr[beg + k]);
            float2 f = __bfloat1622float2(H2[nb * 32 + lane]);
            eA += f.x; oA += f.y;
        }
        float inv = (n > 0) ? (1.f / (float)n) : 0.f;
        float m0 = (eA + eB) * inv;          // channel 2*lane
        float m1 = (oA + oB) * inv;          // channel 2*lane+1
        float2 hs = G2[node * 32 + lane];    // self: channels 2*lane, 2*lane+1
        float h0 = hs.x, h1 = hs.y;

        float a0 = s_b[lane], a1 = s_b[lane + 32];
#pragma unroll
        for (int kk = 0; kk < 32; kk++) {
            float me = __shfl_sync(0xffffffffu, m0, kk);   // ch 2kk
            float mo = __shfl_sync(0xffffffffu, m1, kk);   // ch 2kk+1
            float he = __shfl_sync(0xffffffffu, h0, kk);
            float ho = __shfl_sync(0xffffffffu, h1, kk);
            int c0 = 2 * kk, c1 = 2 * kk + 1;
            a0 = fmaf(me, s_wl[c0 * HID + lane],      fmaf(he, s_wr[c0 * HID + lane],      a0));
            a1 = fmaf(me, s_wl[c0 * HID + lane + 32], fmaf(he, s_wr[c0 * HID + lane + 32], a1));
            a0 = fmaf(mo, s_wl[c1 * HID + lane],      fmaf(ho, s_wr[c1 * HID + lane],      a0));
            a1 = fmaf(mo, s_wl[c1 * HID + lane + 32], fmaf(ho, s_wr[c1 * HID + lane + 32], a1));
        }
        a0 = fmaxf(a0, 0.f);
        a1 = fmaxf(a1, 0.f);

        int g = batch[node];
        red_add_f(&g_psum[g * HID + lane],      a0);
        red_add_f(&g_psum[g * HID + lane + 32], a1);
        if (lane == 0) red_add_f(&g_pcnt[g], 1.f);
    }
}

// ---------------- final: pooled mean @ w_out + b_out ----------------
__global__ void k_final(const float* __restrict__ w_out,
                        const float* __restrict__ b_out,
                        float* __restrict__ out) {
    int g = blockIdx.x * blockDim.x + threadIdx.x;
    if (g >= N_GRAPHS) return;
    float inv = 1.f / fmaxf(g_pcnt[g], 1.f);
    float o0 = b_out[0], o1 = b_out[1];
#pragma unroll
    for (int k = 0; k < HID; k++) {
        float p = g_psum[g * HID + k] * inv;
        o0 = fmaf(p, w_out[k * 2],     o0);
        o1 = fmaf(p, w_out[k * 2 + 1], o1);
    }
    out[g * 2]     = o0;
    out[g * 2 + 1] = o1;
}

extern "C" void kernel_launch(void* const* d_in, const int* in_sizes, int n_in,
                              void* d_out, int out_size) {
    const int*   x_ids = (const int*)d_in[0];
    const int*   edge  = (const int*)d_in[1];
    const int*   src   = edge;
    const int*   dst   = edge + N_EDGES;
    const int*   batch = (const int*)d_in[2];
    const float* embed = (const float*)d_in[3];
    const float* w1_l  = (const float*)d_in[4];
    const float* b1    = (const float*)d_in[5];
    const float* w1_r  = (const float*)d_in[6];
    const float* w2_l  = (const float*)d_in[7];
    const float* b2    = (const float*)d_in[8];
    const float* w2_r  = (const float*)d_in[9];
    const float* w_out = (const float*)d_in[10];
    const float* b_out = (const float*)d_in[11];
    float* out = (float*)d_out;

    k_init<<<1024, 256>>>(x_ids, embed);
    k_hist<<<(N_EDGES + 255) / 256, 256>>>(dst);
    k_scan1<<<SCAN_NB, 256>>>();
    k_scan3<<<SCAN_NB, 256>>>();
    k_fill<<<(N_EDGES + 255) / 256, 256>>>(src, dst);
    k_layer1<<<1184, 256>>>(w1_l, b1, w1_r);          // 8 blocks/SM, 16KB smem
    k_layer2<<<1036, 256>>>(batch, w2_l, b2, w2_r);   // 7 blocks/SM, 32KB smem
    k_final<<<2, 256>>>(w_out, b_out, out);
}

// round 8
// speedup vs baseline: 1.0620x; 1.0620x over previous
#include <cuda_runtime.h>
#include <cuda_bf16.h>

#define N_NODES  50000
#define N_EDGES  1600000
#define N_GRAPHS 512
#define EMB      32
#define HID      64
#define SCAN_NB  ((N_NODES + 255) / 256)   // 196

// ---------------- scratch (device globals: allocation-free) ----------------
__device__ float           g_x   [N_NODES * EMB];   // embedded features (fp32, self term)
__device__ __nv_bfloat16   g_xh  [N_NODES * EMB];   // embedded features (bf16, gather)
__device__ float           g_h1  [N_NODES * HID];   // layer-1 out (fp32, self term)
__device__ __nv_bfloat16   g_h1h [N_NODES * HID];   // layer-1 out (bf16, gather)
__device__ int   g_cnt [N_NODES];         // in-degree
__device__ int   g_ptr [N_NODES];         // CSR row starts
__device__ int   g_cur [N_NODES];         // fill cursors
__device__ int   g_nbr [N_EDGES];         // CSR adjacency (src node per slot)
__device__ int   g_bsum[256];             // scan block totals
__device__ float g_psum[N_GRAPHS * HID];  // pooled sums
__device__ float g_pcnt[N_GRAPHS];        // pooled counts

__device__ __forceinline__ void red_add_f(float* p, float v) {
    asm volatile("red.global.add.f32 [%0], %1;" :: "l"(p), "f"(v) : "memory");
}

// packed d = a*b + c (elementwise on float2) -> single FFMA2 in SASS
__device__ __forceinline__ float2 ffma2(float2 a, float2 b, float2 c) {
    unsigned long long aa, bb, cc, dd;
    aa = *reinterpret_cast<unsigned long long*>(&a);
    bb = *reinterpret_cast<unsigned long long*>(&b);
    cc = *reinterpret_cast<unsigned long long*>(&c);
    asm("fma.rn.f32x2 %0, %1, %2, %3;" : "=l"(dd) : "l"(aa), "l"(bb), "l"(cc));
    return *reinterpret_cast<float2*>(&dd);
}

// ---------------- init: zero counters + embedding gather (fp32 + bf16) ----------------
__global__ void k_init(const int* __restrict__ x_ids,
                       const float* __restrict__ embed) {
    int stride = gridDim.x * blockDim.x;
    int tid = blockIdx.x * blockDim.x + threadIdx.x;

    float4* xv = reinterpret_cast<float4*>(g_x);
    __nv_bfloat162* xh2 = reinterpret_cast<__nv_bfloat162*>(g_xh);
    const float4* emb4 = reinterpret_cast<const float4*>(embed);
    const int n1 = N_NODES * EMB / 4;              // 8 float4 per node
    for (int i = tid; i < n1; i += stride) {
        int node = i >> 3;
        int c    = i & 7;
        float4 v = emb4[(x_ids[node] << 3) + c];
        xv[i] = v;
        xh2[i * 2]     = __float22bfloat162_rn(make_float2(v.x, v.y));
        xh2[i * 2 + 1] = __float22bfloat162_rn(make_float2(v.z, v.w));
    }
    for (int i = tid; i < N_NODES; i += stride) g_cnt[i] = 0;
    for (int i = tid; i < N_GRAPHS * HID; i += stride) g_psum[i] = 0.f;
    for (int i = tid; i < N_GRAPHS; i += stride) g_pcnt[i] = 0.f;
}

// ---------------- CSR build: histogram, scan, fill ----------------
__global__ void k_hist(const int* __restrict__ dst) {
    int e = blockIdx.x * blockDim.x + threadIdx.x;
    if (e < N_EDGES) atomicAdd(&g_cnt[dst[e]], 1);
}

__global__ void k_scan1() {
    __shared__ int sh[256];
    int t = threadIdx.x;
    int i = blockIdx.x * 256 + t;
    int v = (i < N_NODES) ? g_cnt[i] : 0;
    sh[t] = v;
    __syncthreads();
#pragma unroll
    for (int off = 1; off < 256; off <<= 1) {
        int x = (t >= off) ? sh[t - off] : 0;
        __syncthreads();
        sh[t] += x;
        __syncthreads();
    }
    if (i < N_NODES) g_ptr[i] = sh[t] - v;   // exclusive within block
    if (t == 255) g_bsum[blockIdx.x] = sh[255];
}

// scan3 also computes the block-offset prefix (replaces separate scan2)
__global__ void k_scan3() {
    __shared__ int s_off;
    int t = threadIdx.x;
    if (t < 32) {
        int acc = 0;
        for (int j = t; j < blockIdx.x; j += 32) acc += g_bsum[j];
#pragma unroll
        for (int o = 16; o; o >>= 1) acc += __shfl_down_sync(0xffffffffu, acc, o);
        if (t == 0) s_off = acc;
    }
    __syncthreads();
    int i = blockIdx.x * 256 + t;
    if (i < N_NODES) {
        int p = g_ptr[i] + s_off;
        g_ptr[i] = p;
        g_cur[i] = p;
    }
}

__global__ void k_fill(const int* __restrict__ src, const int* __restrict__ dst) {
    int e = blockIdx.x * blockDim.x + threadIdx.x;
    if (e < N_EDGES) {
        int p = atomicAdd(&g_cur[dst[e]], 1);
        g_nbr[p] = src[e];
    }
}

// ---------------- layer 1: bf16 gather-mean + SAGE linear + ReLU (fused) ----------------
// warp per node; lane = channel; matvec via duplicated-smem broadcast + FFMA2
__global__ void __launch_bounds__(256)
k_layer1(const float* __restrict__ w_l,
         const float* __restrict__ b,
         const float* __restrict__ w_r) {
    // weights interleaved as pairs (out ch j, j+32): one LDS.64 per FFMA2
    __shared__ float2 s_wl2[EMB * 32];
    __shared__ float2 s_wr2[EMB * 32];
    __shared__ float2 s_b2[32];
    __shared__ float2 s_m2[8][EMB];   // per-warp staged mean, duplicated (v,v)
    __shared__ float2 s_x2[8][EMB];   // per-warp staged self, duplicated (v,v)
    int t = threadIdx.x;
    for (int i = t; i < EMB * 32; i += blockDim.x) {
        int k = i >> 5, j = i & 31;
        s_wl2[i] = make_float2(w_l[k * HID + j], w_l[k * HID + j + 32]);
        s_wr2[i] = make_float2(w_r[k * HID + j], w_r[k * HID + j + 32]);
    }
    if (t < 32) s_b2[t] = make_float2(b[t], b[t + 32]);
    __syncthreads();

    int lane = t & 31;
    int wi   = t >> 5;                 // warp index in block
    int warp_g = (blockIdx.x * blockDim.x + t) >> 5;
    int nwarps = (gridDim.x * blockDim.x) >> 5;

    for (int node = warp_g; node < N_NODES; node += nwarps) {
        int beg = g_ptr[node];
        int n   = g_cnt[node];
        float s0 = 0.f, s1 = 0.f, s2 = 0.f, s3 = 0.f;
        int k = 0;
        for (; k + 3 < n; k += 4) {
            int n0 = __ldg(&g_nbr[beg + k]);
            int n1 = __ldg(&g_nbr[beg + k + 1]);
            int n2 = __ldg(&g_nbr[beg + k + 2]);
            int n3 = __ldg(&g_nbr[beg + k + 3]);
            s0 += __bfloat162float(g_xh[n0 * EMB + lane]);
            s1 += __bfloat162float(g_xh[n1 * EMB + lane]);
            s2 += __bfloat162float(g_xh[n2 * EMB + lane]);
            s3 += __bfloat162float(g_xh[n3 * EMB + lane]);
        }
        for (; k < n; k++)
            s0 += __bfloat162float(g_xh[__ldg(&g_nbr[beg + k]) * EMB + lane]);
        float m  = (s0 + s1) + (s2 + s3);
        m *= (n > 0) ? (1.f / (float)n) : 0.f;       // mean (deg=0 -> 0)
        float xv = g_x[node * EMB + lane];

        __syncwarp();                                 // prev iter reads done
        s_m2[wi][lane] = make_float2(m, m);
        s_x2[wi][lane] = make_float2(xv, xv);
        __syncwarp();                                 // stage visible

        float2 acc = s_b2[lane];
#pragma unroll
        for (int kk = 0; kk < EMB; kk++) {
            float2 mm = s_m2[wi][kk];                 // (mk, mk) broadcast
            float2 xx = s_x2[wi][kk];
            acc = ffma2(mm, s_wl2[kk * 32 + lane], acc);
            acc = ffma2(xx, s_wr2[kk * 32 + lane], acc);
        }
        float a0 = fmaxf(acc.x, 0.f);
        float a1 = fmaxf(acc.y, 0.f);
        g_h1[node * HID + lane]       = a0;
        g_h1[node * HID + lane + 32]  = a1;
        g_h1h[node * HID + lane]      = __float2bfloat16_rn(a0);
        g_h1h[node * HID + lane + 32] = __float2bfloat16_rn(a1);
    }
}

// ---------------- layer 2: bf16 gather-mean + SAGE linear + ReLU + pool (fused) ----------------
// lane gathers channel pair (2l, 2l+1); matvec via duplicated-smem broadcast + FFMA2
__global__ void __launch_bounds__(256)
k_layer2(const int* __restrict__ batch,
         const float* __restrict__ w_l,
         const float* __restrict__ b,
         const float* __restrict__ w_r) {
    __shared__ float2 s_wl2[HID * 32];
    __shared__ float2 s_wr2[HID * 32];
    __shared__ float2 s_b2[32];
    __shared__ float2 s_m2[8][HID];   // per-warp staged mean, duplicated
    __shared__ float2 s_h2[8][HID];   // per-warp staged self, duplicated
    int t = threadIdx.x;
    for (int i = t; i < HID * 32; i += blockDim.x) {
        int k = i >> 5, j = i & 31;
        s_wl2[i] = make_float2(w_l[k * HID + j], w_l[k * HID + j + 32]);
        s_wr2[i] = make_float2(w_r[k * HID + j], w_r[k * HID + j + 32]);
    }
    if (t < 32) s_b2[t] = make_float2(b[t], b[t + 32]);
    __syncthreads();

    int lane = t & 31;
    int wi   = t >> 5;
    int warp_g = (blockIdx.x * blockDim.x + t) >> 5;
    int nwarps = (gridDim.x * blockDim.x) >> 5;

    const __nv_bfloat162* H2 = reinterpret_cast<const __nv_bfloat162*>(g_h1h);
    const float2*         G2 = reinterpret_cast<const float2*>(g_h1);

    for (int node = warp_g; node < N_NODES; node += nwarps) {
        int beg = g_ptr[node];
        int n   = g_cnt[node];
        float eA = 0.f, oA = 0.f, eB = 0.f, oB = 0.f;
        int k = 0;
        for (; k + 1 < n; k += 2) {
            int n0 = __ldg(&g_nbr[beg + k]);
            int n1 = __ldg(&g_nbr[beg + k + 1]);
            float2 f0 = __bfloat1622float2(H2[n0 * 32 + lane]);
            float2 f1 = __bfloat1622float2(H2[n1 * 32 + lane]);
            eA += f0.x; oA += f0.y;
            eB += f1.x; oB += f1.y;
        }
        for (; k < n; k++) {
            int nb = __ldg(&g_nbr[beg + k]);
            float2 f = __bfloat1622float2(H2[nb * 32 + lane]);
            eA += f.x; oA += f.y;
        }
        float inv = (n > 0) ? (1.f / (float)n) : 0.f;
        float m0 = (eA + eB) * inv;          // input channel 2*lane
        float m1 = (oA + oB) * inv;          // input channel 2*lane+1
        float2 hs = G2[node * 32 + lane];    // self channels 2*lane, 2*lane+1

        __syncwarp();
        s_m2[wi][2 * lane]     = make_float2(m0, m0);
        s_m2[wi][2 * lane + 1] = make_float2(m1, m1);
        s_h2[wi][2 * lane]     = make_float2(hs.x, hs.x);
        s_h2[wi][2 * lane + 1] = make_float2(hs.y, hs.y);
        __syncwarp();

        float2 acc = s_b2[lane];
#pragma unroll
        for (int kk = 0; kk < HID; kk++) {
            float2 mm = s_m2[wi][kk];
            float2 hh = s_h2[wi][kk];
            acc = ffma2(mm, s_wl2[kk * 32 + lane], acc);
            acc = ffma2(hh, s_wr2[kk * 32 + lane], acc);
        }
        float a0 = fmaxf(acc.x, 0.f);
        float a1 = fmaxf(acc.y, 0.f);

        int g = batch[node];
        red_add_f(&g_psum[g * HID + lane],      a0);
        red_add_f(&g_psum[g * HID + lane + 32], a1);
        if (lane == 0) red_add_f(&g_pcnt[g], 1.f);
    }
}

// ---------------- final: pooled mean @ w_out + b_out ----------------
__global__ void k_final(const float* __restrict__ w_out,
                        const float* __restrict__ b_out,
                        float* __restrict__ out) {
    int g = blockIdx.x * blockDim.x + threadIdx.x;
    if (g >= N_GRAPHS) return;
    float inv = 1.f / fmaxf(g_pcnt[g], 1.f);
    float o0 = b_out[0], o1 = b_out[1];
#pragma unroll
    for (int k = 0; k < HID; k++) {
        float p = g_psum[g * HID + k] * inv;
        o0 = fmaf(p, w_out[k * 2],     o0);
        o1 = fmaf(p, w_out[k * 2 + 1], o1);
    }
    out[g * 2]     = o0;
    out[g * 2 + 1] = o1;
}

extern "C" void kernel_launch(void* const* d_in, const int* in_sizes, int n_in,
                              void* d_out, int out_size) {
    const int*   x_ids = (const int*)d_in[0];
    const int*   edge  = (const int*)d_in[1];
    const int*   src   = edge;
    const int*   dst   = edge + N_EDGES;
    const int*   batch = (const int*)d_in[2];
    const float* embed = (const float*)d_in[3];
    const float* w1_l  = (const float*)d_in[4];
    const float* b1    = (const float*)d_in[5];
    const float* w1_r  = (const float*)d_in[6];
    const float* w2_l  = (const float*)d_in[7];
    const float* b2    = (const float*)d_in[8];
    const float* w2_r  = (const float*)d_in[9];
    const float* w_out = (const float*)d_in[10];
    const float* b_out = (const float*)d_in[11];
    float* out = (float*)d_out;

    k_init<<<1024, 256>>>(x_ids, embed);
    k_hist<<<(N_EDGES + 255) / 256, 256>>>(dst);
    k_scan1<<<SCAN_NB, 256>>>();
    k_scan3<<<SCAN_NB, 256>>>();
    k_fill<<<(N_EDGES + 255) / 256, 256>>>(src, dst);
    k_layer1<<<1184, 256>>>(w1_l, b1, w1_r);          // 8 blocks/SM, ~20KB smem
    k_layer2<<<740, 256>>>(batch, w2_l, b2, w2_r);    // 5 blocks/SM, ~41KB smem
    k_final<<<2, 256>>>(w_out, b_out, out);
}